// round 1
// baseline (speedup 1.0000x reference)
#include <cuda_runtime.h>

// Problem constants
#define IN_DIM  8192
#define OUT_DIM 8192

// Tiling
#define THREADS 256
#define VEC 4
#define COLS_PER_BLOCK (THREADS * VEC)          // 1024
#define N_COL_BLOCKS   (OUT_DIM / COLS_PER_BLOCK)  // 8
#define N_ROW_CHUNKS   64
#define ROWS_PER_CHUNK (IN_DIM / N_ROW_CHUNKS)  // 128

// Scratch for partial sums: [chunk][col] for s1 (c*W) and s2 (r*|W|)
__device__ float g_s1[N_ROW_CHUNKS * OUT_DIM];
__device__ float g_s2[N_ROW_CHUNKS * OUT_DIM];

__global__ __launch_bounds__(THREADS)
void ibp_partial_kernel(const float* __restrict__ l,
                        const float* __restrict__ u,
                        const float* __restrict__ w) {
    __shared__ float sc[ROWS_PER_CHUNK];
    __shared__ float sr[ROWS_PER_CHUNK];

    const int col0 = blockIdx.x * COLS_PER_BLOCK + threadIdx.x * VEC;
    const int row0 = blockIdx.y * ROWS_PER_CHUNK;

    // Stage center / radius for this row chunk
    for (int i = threadIdx.x; i < ROWS_PER_CHUNK; i += THREADS) {
        float lv = l[row0 + i];
        float uv = u[row0 + i];
        sc[i] = 0.5f * (lv + uv);
        sr[i] = 0.5f * (uv - lv);
    }
    __syncthreads();

    float s1x = 0.f, s1y = 0.f, s1z = 0.f, s1w = 0.f;
    float s2x = 0.f, s2y = 0.f, s2z = 0.f, s2w = 0.f;

    // Pointer to W[row0][col0] in float4 units; row stride = OUT_DIM/4 float4s
    const float4* __restrict__ wp =
        reinterpret_cast<const float4*>(w + (size_t)row0 * OUT_DIM + col0);
    const size_t rstride = OUT_DIM / 4;

    #pragma unroll 8
    for (int i = 0; i < ROWS_PER_CHUNK; i++) {
        float4 wv = wp[(size_t)i * rstride];
        float c = sc[i];
        float r = sr[i];
        s1x = fmaf(c, wv.x, s1x);
        s1y = fmaf(c, wv.y, s1y);
        s1z = fmaf(c, wv.z, s1z);
        s1w = fmaf(c, wv.w, s1w);
        s2x = fmaf(r, fabsf(wv.x), s2x);
        s2y = fmaf(r, fabsf(wv.y), s2y);
        s2z = fmaf(r, fabsf(wv.z), s2z);
        s2w = fmaf(r, fabsf(wv.w), s2w);
    }

    const size_t base = (size_t)blockIdx.y * OUT_DIM + col0;
    float4 o1 = make_float4(s1x, s1y, s1z, s1w);
    float4 o2 = make_float4(s2x, s2y, s2z, s2w);
    *reinterpret_cast<float4*>(&g_s1[base]) = o1;
    *reinterpret_cast<float4*>(&g_s2[base]) = o2;
}

__global__ __launch_bounds__(THREADS)
void ibp_reduce_kernel(const float* __restrict__ bias,
                       float* __restrict__ out) {
    const int col = blockIdx.x * THREADS + threadIdx.x;
    float s1 = 0.f, s2 = 0.f;
    #pragma unroll 8
    for (int c = 0; c < N_ROW_CHUNKS; c++) {
        s1 += g_s1[(size_t)c * OUT_DIM + col];
        s2 += g_s2[(size_t)c * OUT_DIM + col];
    }
    float b = bias[col];
    out[col]           = s1 - s2 + b;  // bound_l
    out[OUT_DIM + col] = s1 + s2 + b;  // bound_u
}

extern "C" void kernel_launch(void* const* d_in, const int* in_sizes, int n_in,
                              void* d_out, int out_size) {
    const float* l    = (const float*)d_in[0];
    const float* u    = (const float*)d_in[1];
    const float* w    = (const float*)d_in[2];
    const float* bias = (const float*)d_in[3];
    float* out = (float*)d_out;

    dim3 grid(N_COL_BLOCKS, N_ROW_CHUNKS);
    ibp_partial_kernel<<<grid, THREADS>>>(l, u, w);
    ibp_reduce_kernel<<<OUT_DIM / THREADS, THREADS>>>(bias, out);
}

// round 2
// speedup vs baseline: 1.0701x; 1.0701x over previous
#include <cuda_runtime.h>

// Problem constants
#define IN_DIM  8192
#define OUT_DIM 8192

// Partial-kernel tiling: 128 threads x float4 = 512 cols/block
#define P_THREADS 128
#define VEC 4
#define COLS_PER_BLOCK (P_THREADS * VEC)            // 512
#define N_COL_BLOCKS   (OUT_DIM / COLS_PER_BLOCK)   // 16
#define N_ROW_CHUNKS   64
#define ROWS_PER_CHUNK (IN_DIM / N_ROW_CHUNKS)      // 128

// Scratch for partial sums: [chunk][col]
__device__ float g_s1[N_ROW_CHUNKS * OUT_DIM];
__device__ float g_s2[N_ROW_CHUNKS * OUT_DIM];

__global__ __launch_bounds__(P_THREADS)
void ibp_partial_kernel(const float* __restrict__ l,
                        const float* __restrict__ u,
                        const float* __restrict__ w) {
    __shared__ float sc[ROWS_PER_CHUNK];
    __shared__ float sr[ROWS_PER_CHUNK];

    const int col0 = blockIdx.x * COLS_PER_BLOCK + threadIdx.x * VEC;
    const int row0 = blockIdx.y * ROWS_PER_CHUNK;

    for (int i = threadIdx.x; i < ROWS_PER_CHUNK; i += P_THREADS) {
        float lv = l[row0 + i];
        float uv = u[row0 + i];
        sc[i] = 0.5f * (lv + uv);
        sr[i] = 0.5f * (uv - lv);
    }
    __syncthreads();

    float s1x = 0.f, s1y = 0.f, s1z = 0.f, s1w = 0.f;
    float s2x = 0.f, s2y = 0.f, s2z = 0.f, s2w = 0.f;

    const float4* __restrict__ wp =
        reinterpret_cast<const float4*>(w + (size_t)row0 * OUT_DIM + col0);
    const size_t rstride = OUT_DIM / 4;

    #pragma unroll 8
    for (int i = 0; i < ROWS_PER_CHUNK; i++) {
        float4 wv = __ldcs(&wp[(size_t)i * rstride]);   // stream, evict-first
        float c = sc[i];
        float r = sr[i];
        s1x = fmaf(c, wv.x, s1x);
        s1y = fmaf(c, wv.y, s1y);
        s1z = fmaf(c, wv.z, s1z);
        s1w = fmaf(c, wv.w, s1w);
        s2x = fmaf(r, fabsf(wv.x), s2x);
        s2y = fmaf(r, fabsf(wv.y), s2y);
        s2z = fmaf(r, fabsf(wv.z), s2z);
        s2w = fmaf(r, fabsf(wv.w), s2w);
    }

    const size_t base = (size_t)blockIdx.y * OUT_DIM + col0;
    *reinterpret_cast<float4*>(&g_s1[base]) = make_float4(s1x, s1y, s1z, s1w);
    *reinterpret_cast<float4*>(&g_s2[base]) = make_float4(s2x, s2y, s2z, s2w);
}

// Reduce: grid 64 blocks x 256 threads.
// Block handles 128 cols (32 float4). Threads: tx = t%32 (float4 col),
// grp = t/32 (8 groups), each group sums 8 chunks. smem tree-reduce.
#define R_THREADS 256
#define R_COLS4   32          // 128 cols per block
#define R_GROUPS  8
#define R_CHUNKS_PER_GROUP (N_ROW_CHUNKS / R_GROUPS)  // 8

__global__ __launch_bounds__(R_THREADS)
void ibp_reduce_kernel(const float* __restrict__ bias,
                       float* __restrict__ out) {
    __shared__ float4 sm1[R_GROUPS][R_COLS4];
    __shared__ float4 sm2[R_GROUPS][R_COLS4];

    const int tx  = threadIdx.x & 31;     // float4 col within slab
    const int grp = threadIdx.x >> 5;     // chunk group
    const int col4 = blockIdx.x * R_COLS4 + tx;   // float4 index in [0, 2048)

    const float4* p1 = reinterpret_cast<const float4*>(g_s1);
    const float4* p2 = reinterpret_cast<const float4*>(g_s2);
    const size_t cstride = OUT_DIM / 4;   // float4 stride per chunk

    float4 a1 = make_float4(0.f, 0.f, 0.f, 0.f);
    float4 a2 = make_float4(0.f, 0.f, 0.f, 0.f);
    #pragma unroll
    for (int i = 0; i < R_CHUNKS_PER_GROUP; i++) {
        int c = grp * R_CHUNKS_PER_GROUP + i;
        float4 v1 = p1[(size_t)c * cstride + col4];
        float4 v2 = p2[(size_t)c * cstride + col4];
        a1.x += v1.x; a1.y += v1.y; a1.z += v1.z; a1.w += v1.w;
        a2.x += v2.x; a2.y += v2.y; a2.z += v2.z; a2.w += v2.w;
    }
    sm1[grp][tx] = a1;
    sm2[grp][tx] = a2;
    __syncthreads();

    // tree reduce across groups: 8 -> 4 -> 2 -> 1
    #pragma unroll
    for (int s = R_GROUPS / 2; s >= 1; s >>= 1) {
        if (grp < s) {
            float4 b1 = sm1[grp + s][tx];
            float4 b2 = sm2[grp + s][tx];
            a1.x += b1.x; a1.y += b1.y; a1.z += b1.z; a1.w += b1.w;
            a2.x += b2.x; a2.y += b2.y; a2.z += b2.z; a2.w += b2.w;
            sm1[grp][tx] = a1;
            sm2[grp][tx] = a2;
        }
        __syncthreads();
    }

    if (grp == 0) {
        float4 b = reinterpret_cast<const float4*>(bias)[col4];
        float4 lo, hi;
        lo.x = a1.x - a2.x + b.x;  hi.x = a1.x + a2.x + b.x;
        lo.y = a1.y - a2.y + b.y;  hi.y = a1.y + a2.y + b.y;
        lo.z = a1.z - a2.z + b.z;  hi.z = a1.z + a2.z + b.z;
        lo.w = a1.w - a2.w + b.w;  hi.w = a1.w + a2.w + b.w;
        reinterpret_cast<float4*>(out)[col4] = lo;                     // bound_l
        reinterpret_cast<float4*>(out + OUT_DIM)[col4] = hi;           // bound_u
    }
}

extern "C" void kernel_launch(void* const* d_in, const int* in_sizes, int n_in,
                              void* d_out, int out_size) {
    const float* l    = (const float*)d_in[0];
    const float* u    = (const float*)d_in[1];
    const float* w    = (const float*)d_in[2];
    const float* bias = (const float*)d_in[3];
    float* out = (float*)d_out;

    dim3 grid(N_COL_BLOCKS, N_ROW_CHUNKS);   // (16, 64) = 1024 CTAs
    ibp_partial_kernel<<<grid, P_THREADS>>>(l, u, w);
    ibp_reduce_kernel<<<OUT_DIM / (R_COLS4 * 4), R_THREADS>>>(bias, out);  // 64 CTAs
}